// round 14
// baseline (speedup 1.0000x reference)
#include <cuda_runtime.h>
#include <cuda_bf16.h>
#include <stdint.h>
#include <math.h>

// Problem constants (fixed shapes)
#define BB 4
#define LL 4096
#define DD 1024
#define HH 16
#define DH 64
#define NCHUNK 8
#define CHUNKL (LL / NCHUNK)   // 512
#define MTOT (BB * LL)         // 16384

// ===========================================================================
// Scratch (static __device__ arrays; no allocation anywhere)
// ===========================================================================
__device__ __align__(16) float g_qp[(size_t)BB * LL * DD];
__device__ __align__(16) float g_kp[(size_t)BB * LL * DD];
__device__ __align__(16) float g_vp[(size_t)BB * LL * DD];
__device__ __align__(16) float g_kvpart[(size_t)NCHUNK * BB * HH * 2 * DH * DH];
__device__ __align__(16) float g_kv[(size_t)BB * HH * 2 * DH * DH];
// bf16 hi/lo packed operands: row-major, row stride 2048 (cols 0..1023 = hi, 1024..2047 = lo)
__device__ __align__(16) __nv_bfloat16 g_apack[(size_t)MTOT * 2048];
__device__ __align__(16) __nv_bfloat16 g_wpack[(size_t)1024 * 2048];

// ===========================================================================
// pack_hilo: fp32 (rows x 1024) -> bf16 (rows x 2048) [hi | lo]
// ===========================================================================
__global__ void pack_hilo(const float* __restrict__ src, __nv_bfloat16* __restrict__ dst)
{
    size_t idx = (size_t)blockIdx.x * 256 + threadIdx.x;   // group-of-4 index
    size_t row = idx >> 8;
    int c4 = (int)(idx & 255) << 2;
    float4 x = *(const float4*)(src + row * 1024 + c4);
    __nv_bfloat16 h0 = __float2bfloat16(x.x);
    __nv_bfloat16 h1 = __float2bfloat16(x.y);
    __nv_bfloat16 h2 = __float2bfloat16(x.z);
    __nv_bfloat16 h3 = __float2bfloat16(x.w);
    __nv_bfloat16 l0 = __float2bfloat16(x.x - __bfloat162float(h0));
    __nv_bfloat16 l1 = __float2bfloat16(x.y - __bfloat162float(h1));
    __nv_bfloat16 l2 = __float2bfloat16(x.z - __bfloat162float(h2));
    __nv_bfloat16 l3 = __float2bfloat16(x.w - __bfloat162float(h3));
    __nv_bfloat162* ph = (__nv_bfloat162*)(dst + row * 2048 + c4);
    ph[0] = __halves2bfloat162(h0, h1);
    ph[1] = __halves2bfloat162(h2, h3);
    __nv_bfloat162* pl = (__nv_bfloat162*)(dst + row * 2048 + 1024 + c4);
    pl[0] = __halves2bfloat162(l0, l1);
    pl[1] = __halves2bfloat162(l2, l3);
}

// ===========================================================================
// HMMA (mma.sync) bf16-split GEMM: C[m,n] = sum_k A[m,k]*W[n,k] + bias[n]
// A, W packed hi/lo bf16 (row stride 2048). Virtual K' = 3072:
//   region 0: Ahi*Whi, region 1: Ahi*Wlo, region 2: Alo*Whi
// CTA tile 128x128, 8 warps (warp tile m32 x n64), K-chunk 64 bf16,
// cp.async double-buffered smem, ldmatrix operand loads, XOR-128B swizzle.
// ===========================================================================
#define GBM 128
#define GBN 128
#define GSTAGE 32768                       // A 16KB + B 16KB per stage
#define GEMM_SMEM (2 * GSTAGE + 1024)
#define NVCHUNK 48                         // 3 regions x 16 chunks of 64

__device__ __forceinline__ uint32_t smem_u32(const void* p) {
    uint32_t a;
    asm("{ .reg .u64 t; cvta.to.shared.u64 t, %1; cvt.u32.u64 %0, t; }" : "=r"(a) : "l"(p));
    return a;
}

__global__ __launch_bounds__(256)
void gemm_hmma(const __nv_bfloat16* __restrict__ A, const __nv_bfloat16* __restrict__ W,
               const float* __restrict__ bias, float* __restrict__ C)
{
    extern __shared__ char dyn_smem[];
    // 1024-align the stage base (swizzle consistency + clean banking)
    const uint32_t dyn_base = smem_u32(dyn_smem);
    const uint32_t sbase = (dyn_base + 1023) & ~1023u;
    char* sb = dyn_smem + (sbase - dyn_base);

    const int tid = threadIdx.x;
    const int wid = tid >> 5, lane = tid & 31;
    const int wm = wid & 3, wn = wid >> 2;         // warp origin (wm*32, wn*64)
    const int bm = blockIdx.y * GBM;
    const int bn = blockIdx.x * GBN;

    float acc[2][8][4];
    #pragma unroll
    for (int mi = 0; mi < 2; mi++)
        #pragma unroll
        for (int t = 0; t < 8; t++)
            #pragma unroll
            for (int r = 0; r < 4; r++) acc[mi][t][r] = 0.0f;

    // ---- async chunk loader: 128x64 bf16 A tile + 128x64 bf16 B tile ----
    auto load_chunk = [&](int c, int s) {
        const int r = c >> 4, kc = c & 15;
        const int acol = (r == 2 ? 1024 : 0) + kc * 64;   // Alo only in region 2
        const int wcol = (r == 1 ? 1024 : 0) + kc * 64;   // Wlo only in region 1
        const uint32_t abase = sbase + (uint32_t)s * GSTAGE;
        const uint32_t bbase = abase + 16384;
        #pragma unroll
        for (int i = 0; i < 4; ++i) {
            int idx = tid + i * 256;
            int row = idx >> 3, seg = idx & 7;
            uint32_t off = (uint32_t)(row * 128 + seg * 16);
            off ^= (off >> 3) & 0x70;
            const void* gp = A + (size_t)(bm + row) * 2048 + acol + seg * 8;
            asm volatile("cp.async.cg.shared.global [%0], [%1], 16;"
                         :: "r"(abase + off), "l"(gp) : "memory");
        }
        #pragma unroll
        for (int i = 0; i < 4; ++i) {
            int idx = tid + i * 256;
            int row = idx >> 3, seg = idx & 7;
            uint32_t off = (uint32_t)(row * 128 + seg * 16);
            off ^= (off >> 3) & 0x70;
            const void* gp = W + (size_t)(bn + row) * 2048 + wcol + seg * 8;
            asm volatile("cp.async.cg.shared.global [%0], [%1], 16;"
                         :: "r"(bbase + off), "l"(gp) : "memory");
        }
        asm volatile("cp.async.commit_group;" ::: "memory");
    };

    load_chunk(0, 0);

    for (int c = 0; c < NVCHUNK; ++c) {
        asm volatile("cp.async.wait_group 0;" ::: "memory");
        __syncthreads();
        if (c + 1 < NVCHUNK) load_chunk(c + 1, (c + 1) & 1);

        const uint32_t sA = sbase + (uint32_t)(c & 1) * GSTAGE;
        const uint32_t sB = sA + 16384;

        #pragma unroll
        for (int ks = 0; ks < 4; ++ks) {
            const int cb = ks * 32;   // byte offset of this k16 within the 128B row

            uint32_t a[2][4];
            #pragma unroll
            for (int mi = 0; mi < 2; ++mi) {
                int row = wm * 32 + mi * 16 + (lane & 15);
                uint32_t off = (uint32_t)(row * 128 + cb + ((lane >> 4) << 4));
                off ^= (off >> 3) & 0x70;
                asm volatile("ldmatrix.sync.aligned.m8n8.x4.shared.b16 {%0,%1,%2,%3}, [%4];"
                             : "=r"(a[mi][0]), "=r"(a[mi][1]), "=r"(a[mi][2]), "=r"(a[mi][3])
                             : "r"(sA + off));
            }
            uint32_t b[4][4];
            #pragma unroll
            for (int g = 0; g < 4; ++g) {
                int nrow = wn * 64 + g * 16 + ((lane >> 3) & 1) * 8 + (lane & 7);
                uint32_t off = (uint32_t)(nrow * 128 + cb + ((lane >> 4) << 4));
                off ^= (off >> 3) & 0x70;
                asm volatile("ldmatrix.sync.aligned.m8n8.x4.shared.b16 {%0,%1,%2,%3}, [%4];"
                             : "=r"(b[g][0]), "=r"(b[g][1]), "=r"(b[g][2]), "=r"(b[g][3])
                             : "r"(sB + off));
            }
            #pragma unroll
            for (int mi = 0; mi < 2; ++mi)
                #pragma unroll
                for (int t = 0; t < 8; ++t) {
                    const int g = t >> 1, hi = t & 1;
                    asm volatile(
                        "mma.sync.aligned.m16n8k16.row.col.f32.bf16.bf16.f32 "
                        "{%0,%1,%2,%3}, {%4,%5,%6,%7}, {%8,%9}, {%0,%1,%2,%3};"
                        : "+f"(acc[mi][t][0]), "+f"(acc[mi][t][1]),
                          "+f"(acc[mi][t][2]), "+f"(acc[mi][t][3])
                        : "r"(a[mi][0]), "r"(a[mi][1]), "r"(a[mi][2]), "r"(a[mi][3]),
                          "r"(b[g][hi]), "r"(b[g][2 + hi]));
                }
        }
    }

    // ---- epilogue: add bias, store fp32 ----
    const int g4 = lane >> 2, t4 = lane & 3;
    #pragma unroll
    for (int mi = 0; mi < 2; ++mi) {
        const int r0 = bm + wm * 32 + mi * 16 + g4;
        #pragma unroll
        for (int t = 0; t < 8; ++t) {
            const int col = bn + wn * 64 + t * 8 + t4 * 2;
            float2 bv = *(const float2*)(bias + col);
            float2 v0, v1;
            v0.x = acc[mi][t][0] + bv.x; v0.y = acc[mi][t][1] + bv.y;
            v1.x = acc[mi][t][2] + bv.x; v1.y = acc[mi][t][3] + bv.y;
            *(float2*)(C + (size_t)r0 * DD + col) = v0;
            *(float2*)(C + (size_t)(r0 + 8) * DD + col) = v1;
        }
    }
}

// ===========================================================================
// Q/K epilogue (in place): sigmoid, (K: /L2), L2-normalize each 64-elem head
// ===========================================================================
__global__ void qk_epilogue()
{
    const int warp = threadIdx.x >> 5;
    const int lane = threadIdx.x & 31;
    const size_t g = (size_t)blockIdx.x * 8 + warp;
    float* p = blockIdx.y ? g_kp : g_qp;
    const float pre = blockIdx.y ? (1.0f / (float)LL) : 1.0f;

    const size_t base = g * 64;
    float x0 = p[base + lane];
    float x1 = p[base + lane + 32];
    float s0 = pre / (1.0f + expf(-x0));
    float s1 = pre / (1.0f + expf(-x1));
    float ss = s0 * s0 + s1 * s1;
    #pragma unroll
    for (int off = 16; off > 0; off >>= 1)
        ss += __shfl_xor_sync(0xffffffffu, ss, off);
    float sc = 1.0f / fmaxf(sqrtf(ss), 1e-12f);
    p[base + lane]      = s0 * sc;
    p[base + lane + 32] = s1 * sc;
}

// ===========================================================================
// kv partial sums (deterministic), then reduce
// ===========================================================================
__global__ __launch_bounds__(256, 4)
void kv_partial(const float* __restrict__ mask)
{
    const int bh = blockIdx.x;
    const int chunk = blockIdx.y;
    const int b = bh >> 4, h = bh & 15;

    __shared__ float sK[8][64];
    __shared__ float sV[8][64];

    const int t = threadIdx.x;
    const int i = t >> 4, j = t & 15;
    const int l0base = chunk * CHUNKL;

    float accp[4][4], accm[4][4];
    #pragma unroll
    for (int a = 0; a < 4; a++)
        #pragma unroll
        for (int c = 0; c < 4; c++) { accp[a][c] = 0.0f; accm[a][c] = 0.0f; }

    for (int l0 = 0; l0 < CHUNKL; l0 += 8) {
        __syncthreads();
        if (t < 128) {
            int lrow = t >> 4, c4 = (t & 15) << 2;
            int l = l0base + l0 + lrow;
            float4 k4 = *(const float4*)(g_kp + ((size_t)(b * LL + l)) * DD + h * 64 + c4);
            *(float4*)&sK[lrow][c4] = k4;
        } else {
            int tt = t - 128;
            int lrow = tt >> 4, c4 = (tt & 15) << 2;
            int l = l0base + l0 + lrow;
            float m = mask[b * LL + l];
            float4 v4 = *(const float4*)(g_vp + ((size_t)(b * LL + l)) * DD + h * 64 + c4);
            v4.x *= m; v4.y *= m; v4.z *= m; v4.w *= m;
            *(float4*)&sV[lrow][c4] = v4;
        }
        __syncthreads();
        #pragma unroll
        for (int ll = 0; ll < 8; ll++) {
            float4 k4 = *(const float4*)&sK[ll][i * 4];
            float4 v4 = *(const float4*)&sV[ll][j * 4];
            float kk[4] = {k4.x, k4.y, k4.z, k4.w};
            float vv[4] = {v4.x, v4.y, v4.z, v4.w};
            float vps[4], vms[4];
            #pragma unroll
            for (int c = 0; c < 4; c++) {
                vps[c] = fmaxf(vv[c], 0.0f);
                vms[c] = vv[c] - vps[c];
            }
            #pragma unroll
            for (int a = 0; a < 4; a++)
                #pragma unroll
                for (int c = 0; c < 4; c++) {
                    accp[a][c] = fmaf(kk[a], vps[c], accp[a][c]);
                    accm[a][c] = fmaf(kk[a], vms[c], accm[a][c]);
                }
        }
    }

    const size_t base = ((size_t)(chunk * 64 + bh)) * 2 * (DH * DH);
    #pragma unroll
    for (int a = 0; a < 4; a++) {
        int d = i * 4 + a;
        float4 p4 = make_float4(accp[a][0], accp[a][1], accp[a][2], accp[a][3]);
        float4 m4 = make_float4(accm[a][0], accm[a][1], accm[a][2], accm[a][3]);
        *(float4*)(g_kvpart + base + d * 64 + j * 4) = p4;
        *(float4*)(g_kvpart + base + DH * DH + d * 64 + j * 4) = m4;
    }
}

__global__ void kv_reduce()
{
    const size_t stride = (size_t)BB * HH * 2 * DH * DH;
    size_t idx = (size_t)blockIdx.x * 256 + threadIdx.x;
    float s = 0.0f;
    #pragma unroll
    for (int ch = 0; ch < NCHUNK; ch++)
        s += g_kvpart[(size_t)ch * stride + idx];
    g_kv[idx] = s;
}

// ===========================================================================
// Apply: heads = l2norm(Q@kv+) + l2norm(Q@kv-); output packed bf16 hi/lo
// straight into g_apack (for the Wo GEMM).
// ===========================================================================
__global__ __launch_bounds__(256)
void qkv_apply()
{
    const int bh = blockIdx.x;
    const int tile = blockIdx.y;
    const int b = bh >> 4, h = bh & 15;

    __shared__ float Qs[64][64];
    __shared__ float kvp[64][64];
    __shared__ float kvm[64][64];

    const int t = threadIdx.x;
    const size_t kvbase = (size_t)bh * 2 * (DH * DH);

    #pragma unroll
    for (int r = 0; r < 4; r++) {
        int idx = r * 256 + t;
        ((float4*)kvp)[idx] = ((const float4*)(g_kv + kvbase))[idx];
        ((float4*)kvm)[idx] = ((const float4*)(g_kv + kvbase + DH * DH))[idx];
    }
    const int l0 = tile * 64;
    #pragma unroll
    for (int r = 0; r < 4; r++) {
        int tok = r * 16 + (t >> 4);
        int d4 = (t & 15) << 2;
        float4 q4 = *(const float4*)(g_qp + ((size_t)(b * LL + l0 + tok)) * DD + h * 64 + d4);
        Qs[d4 + 0][tok] = q4.x; Qs[d4 + 1][tok] = q4.y;
        Qs[d4 + 2][tok] = q4.z; Qs[d4 + 3][tok] = q4.w;
    }
    __syncthreads();

    const int i = t >> 4, j = t & 15;
    float accp[4][4], accm[4][4];
    #pragma unroll
    for (int a = 0; a < 4; a++)
        #pragma unroll
        for (int c = 0; c < 4; c++) { accp[a][c] = 0.0f; accm[a][c] = 0.0f; }

    #pragma unroll 8
    for (int d = 0; d < 64; d++) {
        float4 q4 = *(const float4*)&Qs[d][i * 4];
        float4 p4 = *(const float4*)&kvp[d][j * 4];
        float4 m4 = *(const float4*)&kvm[d][j * 4];
        float qq[4] = {q4.x, q4.y, q4.z, q4.w};
        float pp[4] = {p4.x, p4.y, p4.z, p4.w};
        float mm[4] = {m4.x, m4.y, m4.z, m4.w};
        #pragma unroll
        for (int a = 0; a < 4; a++)
            #pragma unroll
            for (int c = 0; c < 4; c++) {
                accp[a][c] = fmaf(qq[a], pp[c], accp[a][c]);
                accm[a][c] = fmaf(qq[a], mm[c], accm[a][c]);
            }
    }

    #pragma unroll
    for (int a = 0; a < 4; a++) {
        float sp = accp[a][0] * accp[a][0] + accp[a][1] * accp[a][1]
                 + accp[a][2] * accp[a][2] + accp[a][3] * accp[a][3];
        float sm = accm[a][0] * accm[a][0] + accm[a][1] * accm[a][1]
                 + accm[a][2] * accm[a][2] + accm[a][3] * accm[a][3];
        #pragma unroll
        for (int off = 8; off > 0; off >>= 1) {
            sp += __shfl_xor_sync(0xffffffffu, sp, off, 16);
            sm += __shfl_xor_sync(0xffffffffu, sm, off, 16);
        }
        float scp = 1.0f / fmaxf(sqrtf(sp), 1e-12f);
        float scm = 1.0f / fmaxf(sqrtf(sm), 1e-12f);
        int tok = i * 4 + a;
        float ox = accp[a][0] * scp + accm[a][0] * scm;
        float oy = accp[a][1] * scp + accm[a][1] * scm;
        float oz = accp[a][2] * scp + accm[a][2] * scm;
        float ow = accp[a][3] * scp + accm[a][3] * scm;

        __nv_bfloat16 h0 = __float2bfloat16(ox);
        __nv_bfloat16 h1 = __float2bfloat16(oy);
        __nv_bfloat16 h2 = __float2bfloat16(oz);
        __nv_bfloat16 h3 = __float2bfloat16(ow);
        __nv_bfloat16 l0b = __float2bfloat16(ox - __bfloat162float(h0));
        __nv_bfloat16 l1b = __float2bfloat16(oy - __bfloat162float(h1));
        __nv_bfloat16 l2b = __float2bfloat16(oz - __bfloat162float(h2));
        __nv_bfloat16 l3b = __float2bfloat16(ow - __bfloat162float(h3));

        size_t m = (size_t)(b * LL + l0 + tok);
        int col = h * 64 + j * 4;
        __nv_bfloat162* ph = (__nv_bfloat162*)(g_apack + m * 2048 + col);
        ph[0] = __halves2bfloat162(h0, h1);
        ph[1] = __halves2bfloat162(h2, h3);
        __nv_bfloat162* pl = (__nv_bfloat162*)(g_apack + m * 2048 + 1024 + col);
        pl[0] = __halves2bfloat162(l0b, l1b);
        pl[1] = __halves2bfloat162(l2b, l3b);
    }
}

// ===========================================================================
// Launch
// ===========================================================================
extern "C" void kernel_launch(void* const* d_in, const int* in_sizes, int n_in,
                              void* d_out, int out_size)
{
    (void)in_sizes; (void)n_in; (void)out_size;
    const float* q    = (const float*)d_in[0];
    const float* v    = (const float*)d_in[1];
    const float* k    = (const float*)d_in[2];
    const float* mask = (const float*)d_in[3];
    const float* Wq   = (const float*)d_in[4];
    const float* bq   = (const float*)d_in[5];
    const float* Wk   = (const float*)d_in[6];
    const float* bk   = (const float*)d_in[7];
    const float* Wv   = (const float*)d_in[8];
    const float* bv   = (const float*)d_in[9];
    const float* Wo   = (const float*)d_in[10];
    const float* bo   = (const float*)d_in[11];
    float* out = (float*)d_out;

    float *p_qp, *p_kp, *p_vp;
    __nv_bfloat16 *p_apack, *p_wpack;
    cudaGetSymbolAddress((void**)&p_qp, g_qp);
    cudaGetSymbolAddress((void**)&p_kp, g_kp);
    cudaGetSymbolAddress((void**)&p_vp, g_vp);
    cudaGetSymbolAddress((void**)&p_apack, g_apack);
    cudaGetSymbolAddress((void**)&p_wpack, g_wpack);

    static bool attr_set = false;
    if (!attr_set) {
        cudaFuncSetAttribute(gemm_hmma, cudaFuncAttributeMaxDynamicSharedMemorySize, GEMM_SMEM);
        attr_set = true;
    }

    dim3 ggrid(DD / GBN, MTOT / GBM);  // (8, 128)

    // Q projection
    pack_hilo<<<MTOT, 256>>>(q, p_apack);
    pack_hilo<<<1024, 256>>>(Wq, p_wpack);
    gemm_hmma<<<ggrid, 256, GEMM_SMEM>>>(p_apack, p_wpack, bq, p_qp);
    // K projection
    pack_hilo<<<MTOT, 256>>>(k, p_apack);
    pack_hilo<<<1024, 256>>>(Wk, p_wpack);
    gemm_hmma<<<ggrid, 256, GEMM_SMEM>>>(p_apack, p_wpack, bk, p_kp);
    // V projection
    pack_hilo<<<MTOT, 256>>>(v, p_apack);
    pack_hilo<<<1024, 256>>>(Wv, p_wpack);
    gemm_hmma<<<ggrid, 256, GEMM_SMEM>>>(p_apack, p_wpack, bv, p_vp);

    // sigmoid + (K: /L2) + L2 normalize, in place
    qk_epilogue<<<dim3((BB * LL * HH) / 8, 2), 256>>>();

    // kv matrices (deterministic partial + reduce)
    kv_partial<<<dim3(BB * HH, NCHUNK), 256>>>(mask);
    kv_reduce<<<(BB * HH * 2 * DH * DH) / 256, 256>>>();

    // heads = l2norm(Q@kv+) + l2norm(Q@kv-), packed bf16 hi/lo into g_apack
    qkv_apply<<<dim3(BB * HH, LL / 64), 256>>>();

    // Output projection
    pack_hilo<<<1024, 256>>>(Wo, p_wpack);
    gemm_hmma<<<ggrid, 256, GEMM_SMEM>>>(p_apack, p_wpack, bo, out);
}

// round 15
// speedup vs baseline: 1.0151x; 1.0151x over previous
#include <cuda_runtime.h>
#include <cuda_bf16.h>
#include <stdint.h>
#include <math.h>

// Problem constants (fixed shapes)
#define BB 4
#define LL 4096
#define DD 1024
#define HH 16
#define DH 64
#define NCHUNK 8
#define CHUNKL (LL / NCHUNK)   // 512
#define MTOT (BB * LL)         // 16384

// ===========================================================================
// Scratch (static __device__ arrays; no allocation anywhere)
// ===========================================================================
__device__ __align__(16) float g_qp[(size_t)BB * LL * DD];
__device__ __align__(16) float g_kp[(size_t)BB * LL * DD];
__device__ __align__(16) float g_vp[(size_t)BB * LL * DD];
__device__ __align__(16) float g_kvpart[(size_t)NCHUNK * BB * HH * 2 * DH * DH];
__device__ __align__(16) float g_kv[(size_t)BB * HH * 2 * DH * DH];
// bf16 hi/lo packed operands: row-major, row stride 2048 (cols 0..1023 = hi, 1024..2047 = lo)
__device__ __align__(16) __nv_bfloat16 g_apack[(size_t)MTOT * 2048];
__device__ __align__(16) __nv_bfloat16 g_wpack[(size_t)1024 * 2048];

// ===========================================================================
// pack_hilo: fp32 (rows x 1024) -> bf16 (rows x 2048) [hi | lo]
// ===========================================================================
__global__ void pack_hilo(const float* __restrict__ src, __nv_bfloat16* __restrict__ dst)
{
    size_t idx = (size_t)blockIdx.x * 256 + threadIdx.x;   // group-of-4 index
    size_t row = idx >> 8;
    int c4 = (int)(idx & 255) << 2;
    float4 x = *(const float4*)(src + row * 1024 + c4);
    __nv_bfloat16 h0 = __float2bfloat16(x.x);
    __nv_bfloat16 h1 = __float2bfloat16(x.y);
    __nv_bfloat16 h2 = __float2bfloat16(x.z);
    __nv_bfloat16 h3 = __float2bfloat16(x.w);
    __nv_bfloat16 l0 = __float2bfloat16(x.x - __bfloat162float(h0));
    __nv_bfloat16 l1 = __float2bfloat16(x.y - __bfloat162float(h1));
    __nv_bfloat16 l2 = __float2bfloat16(x.z - __bfloat162float(h2));
    __nv_bfloat16 l3 = __float2bfloat16(x.w - __bfloat162float(h3));
    __nv_bfloat162* ph = (__nv_bfloat162*)(dst + row * 2048 + c4);
    ph[0] = __halves2bfloat162(h0, h1);
    ph[1] = __halves2bfloat162(h2, h3);
    __nv_bfloat162* pl = (__nv_bfloat162*)(dst + row * 2048 + 1024 + c4);
    pl[0] = __halves2bfloat162(l0, l1);
    pl[1] = __halves2bfloat162(l2, l3);
}

// ===========================================================================
// HMMA (mma.sync) bf16-split GEMM: C[m,n] = sum_k A[m,k]*W[n,k] + bias[n]
// A, W packed hi/lo bf16 (row stride 2048). Virtual K' = 3072:
//   region 0: Ahi*Whi, region 1: Ahi*Wlo, region 2: Alo*Whi
// CTA tile 128x128, 8 warps (warp tile m32 x n64), K-chunk 64 bf16,
// cp.async double-buffered smem, ldmatrix operand loads, XOR-128B swizzle.
// ===========================================================================
#define GBM 128
#define GBN 128
#define GSTAGE 32768                       // A 16KB + B 16KB per stage
#define GEMM_SMEM (2 * GSTAGE + 1024)
#define NVCHUNK 48                         // 3 regions x 16 chunks of 64

__device__ __forceinline__ uint32_t smem_u32(const void* p) {
    uint32_t a;
    asm("{ .reg .u64 t; cvta.to.shared.u64 t, %1; cvt.u32.u64 %0, t; }" : "=r"(a) : "l"(p));
    return a;
}

__global__ __launch_bounds__(256)
void gemm_hmma(const __nv_bfloat16* __restrict__ A, const __nv_bfloat16* __restrict__ W,
               const float* __restrict__ bias, float* __restrict__ C)
{
    extern __shared__ char dyn_smem[];
    // 1024-align the stage base (swizzle consistency + clean banking)
    const uint32_t dyn_base = smem_u32(dyn_smem);
    const uint32_t sbase = (dyn_base + 1023) & ~1023u;
    char* sb = dyn_smem + (sbase - dyn_base);

    const int tid = threadIdx.x;
    const int wid = tid >> 5, lane = tid & 31;
    const int wm = wid & 3, wn = wid >> 2;         // warp origin (wm*32, wn*64)
    const int bm = blockIdx.y * GBM;
    const int bn = blockIdx.x * GBN;

    float acc[2][8][4];
    #pragma unroll
    for (int mi = 0; mi < 2; mi++)
        #pragma unroll
        for (int t = 0; t < 8; t++)
            #pragma unroll
            for (int r = 0; r < 4; r++) acc[mi][t][r] = 0.0f;

    // ---- async chunk loader: 128x64 bf16 A tile + 128x64 bf16 B tile ----
    auto load_chunk = [&](int c, int s) {
        const int r = c >> 4, kc = c & 15;
        const int acol = (r == 2 ? 1024 : 0) + kc * 64;   // Alo only in region 2
        const int wcol = (r == 1 ? 1024 : 0) + kc * 64;   // Wlo only in region 1
        const uint32_t abase = sbase + (uint32_t)s * GSTAGE;
        const uint32_t bbase = abase + 16384;
        #pragma unroll
        for (int i = 0; i < 4; ++i) {
            int idx = tid + i * 256;
            int row = idx >> 3, seg = idx & 7;
            uint32_t off = (uint32_t)(row * 128 + seg * 16);
            off ^= (off >> 3) & 0x70;
            const void* gp = A + (size_t)(bm + row) * 2048 + acol + seg * 8;
            asm volatile("cp.async.cg.shared.global [%0], [%1], 16;"
                         :: "r"(abase + off), "l"(gp) : "memory");
        }
        #pragma unroll
        for (int i = 0; i < 4; ++i) {
            int idx = tid + i * 256;
            int row = idx >> 3, seg = idx & 7;
            uint32_t off = (uint32_t)(row * 128 + seg * 16);
            off ^= (off >> 3) & 0x70;
            const void* gp = W + (size_t)(bn + row) * 2048 + wcol + seg * 8;
            asm volatile("cp.async.cg.shared.global [%0], [%1], 16;"
                         :: "r"(bbase + off), "l"(gp) : "memory");
        }
        asm volatile("cp.async.commit_group;" ::: "memory");
    };

    load_chunk(0, 0);

    for (int c = 0; c < NVCHUNK; ++c) {
        asm volatile("cp.async.wait_group 0;" ::: "memory");
        __syncthreads();
        if (c + 1 < NVCHUNK) load_chunk(c + 1, (c + 1) & 1);

        const uint32_t sA = sbase + (uint32_t)(c & 1) * GSTAGE;
        const uint32_t sB = sA + 16384;

        #pragma unroll
        for (int ks = 0; ks < 4; ++ks) {
            const int cb = ks * 32;   // byte offset of this k16 within the 128B row

            uint32_t a[2][4];
            #pragma unroll
            for (int mi = 0; mi < 2; ++mi) {
                int row = wm * 32 + mi * 16 + (lane & 15);
                uint32_t off = (uint32_t)(row * 128 + cb + ((lane >> 4) << 4));
                off ^= (off >> 3) & 0x70;
                asm volatile("ldmatrix.sync.aligned.m8n8.x4.shared.b16 {%0,%1,%2,%3}, [%4];"
                             : "=r"(a[mi][0]), "=r"(a[mi][1]), "=r"(a[mi][2]), "=r"(a[mi][3])
                             : "r"(sA + off));
            }
            uint32_t b[4][4];
            #pragma unroll
            for (int g = 0; g < 4; ++g) {
                int nrow = wn * 64 + g * 16 + ((lane >> 3) & 1) * 8 + (lane & 7);
                uint32_t off = (uint32_t)(nrow * 128 + cb + ((lane >> 4) << 4));
                off ^= (off >> 3) & 0x70;
                asm volatile("ldmatrix.sync.aligned.m8n8.x4.shared.b16 {%0,%1,%2,%3}, [%4];"
                             : "=r"(b[g][0]), "=r"(b[g][1]), "=r"(b[g][2]), "=r"(b[g][3])
                             : "r"(sB + off));
            }
            #pragma unroll
            for (int mi = 0; mi < 2; ++mi)
                #pragma unroll
                for (int t = 0; t < 8; ++t) {
                    const int g = t >> 1, hi = t & 1;
                    asm volatile(
                        "mma.sync.aligned.m16n8k16.row.col.f32.bf16.bf16.f32 "
                        "{%0,%1,%2,%3}, {%4,%5,%6,%7}, {%8,%9}, {%0,%1,%2,%3};"
                        : "+f"(acc[mi][t][0]), "+f"(acc[mi][t][1]),
                          "+f"(acc[mi][t][2]), "+f"(acc[mi][t][3])
                        : "r"(a[mi][0]), "r"(a[mi][1]), "r"(a[mi][2]), "r"(a[mi][3]),
                          "r"(b[g][hi]), "r"(b[g][2 + hi]));
                }
        }
    }

    // ---- epilogue: add bias, store fp32 ----
    const int g4 = lane >> 2, t4 = lane & 3;
    #pragma unroll
    for (int mi = 0; mi < 2; ++mi) {
        const int r0 = bm + wm * 32 + mi * 16 + g4;
        #pragma unroll
        for (int t = 0; t < 8; ++t) {
            const int col = bn + wn * 64 + t * 8 + t4 * 2;
            float2 bv = *(const float2*)(bias + col);
            float2 v0, v1;
            v0.x = acc[mi][t][0] + bv.x; v0.y = acc[mi][t][1] + bv.y;
            v1.x = acc[mi][t][2] + bv.x; v1.y = acc[mi][t][3] + bv.y;
            *(float2*)(C + (size_t)r0 * DD + col) = v0;
            *(float2*)(C + (size_t)(r0 + 8) * DD + col) = v1;
        }
    }
}

// ===========================================================================
// Q/K epilogue (in place): sigmoid, (K: /L2), L2-normalize each 64-elem head
// ===========================================================================
__global__ void qk_epilogue()
{
    const int warp = threadIdx.x >> 5;
    const int lane = threadIdx.x & 31;
    const size_t g = (size_t)blockIdx.x * 8 + warp;
    float* p = blockIdx.y ? g_kp : g_qp;
    const float pre = blockIdx.y ? (1.0f / (float)LL) : 1.0f;

    const size_t base = g * 64;
    float x0 = p[base + lane];
    float x1 = p[base + lane + 32];
    float s0 = pre / (1.0f + expf(-x0));
    float s1 = pre / (1.0f + expf(-x1));
    float ss = s0 * s0 + s1 * s1;
    #pragma unroll
    for (int off = 16; off > 0; off >>= 1)
        ss += __shfl_xor_sync(0xffffffffu, ss, off);
    float sc = 1.0f / fmaxf(sqrtf(ss), 1e-12f);
    p[base + lane]      = s0 * sc;
    p[base + lane + 32] = s1 * sc;
}

// ===========================================================================
// kv partial sums (deterministic), then reduce
// ===========================================================================
__global__ __launch_bounds__(256, 4)
void kv_partial(const float* __restrict__ mask)
{
    const int bh = blockIdx.x;
    const int chunk = blockIdx.y;
    const int b = bh >> 4, h = bh & 15;

    __shared__ float sK[8][64];
    __shared__ float sV[8][64];

    const int t = threadIdx.x;
    const int i = t >> 4, j = t & 15;
    const int l0base = chunk * CHUNKL;

    float accp[4][4], accm[4][4];
    #pragma unroll
    for (int a = 0; a < 4; a++)
        #pragma unroll
        for (int c = 0; c < 4; c++) { accp[a][c] = 0.0f; accm[a][c] = 0.0f; }

    for (int l0 = 0; l0 < CHUNKL; l0 += 8) {
        __syncthreads();
        if (t < 128) {
            int lrow = t >> 4, c4 = (t & 15) << 2;
            int l = l0base + l0 + lrow;
            float4 k4 = *(const float4*)(g_kp + ((size_t)(b * LL + l)) * DD + h * 64 + c4);
            *(float4*)&sK[lrow][c4] = k4;
        } else {
            int tt = t - 128;
            int lrow = tt >> 4, c4 = (tt & 15) << 2;
            int l = l0base + l0 + lrow;
            float m = mask[b * LL + l];
            float4 v4 = *(const float4*)(g_vp + ((size_t)(b * LL + l)) * DD + h * 64 + c4);
            v4.x *= m; v4.y *= m; v4.z *= m; v4.w *= m;
            *(float4*)&sV[lrow][c4] = v4;
        }
        __syncthreads();
        #pragma unroll
        for (int ll = 0; ll < 8; ll++) {
            float4 k4 = *(const float4*)&sK[ll][i * 4];
            float4 v4 = *(const float4*)&sV[ll][j * 4];
            float kk[4] = {k4.x, k4.y, k4.z, k4.w};
            float vv[4] = {v4.x, v4.y, v4.z, v4.w};
            float vps[4], vms[4];
            #pragma unroll
            for (int c = 0; c < 4; c++) {
                vps[c] = fmaxf(vv[c], 0.0f);
                vms[c] = vv[c] - vps[c];
            }
            #pragma unroll
            for (int a = 0; a < 4; a++)
                #pragma unroll
                for (int c = 0; c < 4; c++) {
                    accp[a][c] = fmaf(kk[a], vps[c], accp[a][c]);
                    accm[a][c] = fmaf(kk[a], vms[c], accm[a][c]);
                }
        }
    }

    const size_t base = ((size_t)(chunk * 64 + bh)) * 2 * (DH * DH);
    #pragma unroll
    for (int a = 0; a < 4; a++) {
        int d = i * 4 + a;
        float4 p4 = make_float4(accp[a][0], accp[a][1], accp[a][2], accp[a][3]);
        float4 m4 = make_float4(accm[a][0], accm[a][1], accm[a][2], accm[a][3]);
        *(float4*)(g_kvpart + base + d * 64 + j * 4) = p4;
        *(float4*)(g_kvpart + base + DH * DH + d * 64 + j * 4) = m4;
    }
}

__global__ void kv_reduce()
{
    const size_t stride = (size_t)BB * HH * 2 * DH * DH;
    size_t idx = (size_t)blockIdx.x * 256 + threadIdx.x;
    float s = 0.0f;
    #pragma unroll
    for (int ch = 0; ch < NCHUNK; ch++)
        s += g_kvpart[(size_t)ch * stride + idx];
    g_kv[idx] = s;
}

// ===========================================================================
// Apply: heads = l2norm(Q@kv+) + l2norm(Q@kv-); output packed bf16 hi/lo
// straight into g_apack (for the Wo GEMM).
// ===========================================================================
__global__ __launch_bounds__(256)
void qkv_apply()
{
    const int bh = blockIdx.x;
    const int tile = blockIdx.y;
    const int b = bh >> 4, h = bh & 15;

    __shared__ float Qs[64][64];
    __shared__ float kvp[64][64];
    __shared__ float kvm[64][64];

    const int t = threadIdx.x;
    const size_t kvbase = (size_t)bh * 2 * (DH * DH);

    #pragma unroll
    for (int r = 0; r < 4; r++) {
        int idx = r * 256 + t;
        ((float4*)kvp)[idx] = ((const float4*)(g_kv + kvbase))[idx];
        ((float4*)kvm)[idx] = ((const float4*)(g_kv + kvbase + DH * DH))[idx];
    }
    const int l0 = tile * 64;
    #pragma unroll
    for (int r = 0; r < 4; r++) {
        int tok = r * 16 + (t >> 4);
        int d4 = (t & 15) << 2;
        float4 q4 = *(const float4*)(g_qp + ((size_t)(b * LL + l0 + tok)) * DD + h * 64 + d4);
        Qs[d4 + 0][tok] = q4.x; Qs[d4 + 1][tok] = q4.y;
        Qs[d4 + 2][tok] = q4.z; Qs[d4 + 3][tok] = q4.w;
    }
    __syncthreads();

    const int i = t >> 4, j = t & 15;
    float accp[4][4], accm[4][4];
    #pragma unroll
    for (int a = 0; a < 4; a++)
        #pragma unroll
        for (int c = 0; c < 4; c++) { accp[a][c] = 0.0f; accm[a][c] = 0.0f; }

    #pragma unroll 8
    for (int d = 0; d < 64; d++) {
        float4 q4 = *(const float4*)&Qs[d][i * 4];
        float4 p4 = *(const float4*)&kvp[d][j * 4];
        float4 m4 = *(const float4*)&kvm[d][j * 4];
        float qq[4] = {q4.x, q4.y, q4.z, q4.w};
        float pp[4] = {p4.x, p4.y, p4.z, p4.w};
        float mm[4] = {m4.x, m4.y, m4.z, m4.w};
        #pragma unroll
        for (int a = 0; a < 4; a++)
            #pragma unroll
            for (int c = 0; c < 4; c++) {
                accp[a][c] = fmaf(qq[a], pp[c], accp[a][c]);
                accm[a][c] = fmaf(qq[a], mm[c], accm[a][c]);
            }
    }

    #pragma unroll
    for (int a = 0; a < 4; a++) {
        float sp = accp[a][0] * accp[a][0] + accp[a][1] * accp[a][1]
                 + accp[a][2] * accp[a][2] + accp[a][3] * accp[a][3];
        float sm = accm[a][0] * accm[a][0] + accm[a][1] * accm[a][1]
                 + accm[a][2] * accm[a][2] + accm[a][3] * accm[a][3];
        #pragma unroll
        for (int off = 8; off > 0; off >>= 1) {
            sp += __shfl_xor_sync(0xffffffffu, sp, off, 16);
            sm += __shfl_xor_sync(0xffffffffu, sm, off, 16);
        }
        float scp = 1.0f / fmaxf(sqrtf(sp), 1e-12f);
        float scm = 1.0f / fmaxf(sqrtf(sm), 1e-12f);
        int tok = i * 4 + a;
        float ox = accp[a][0] * scp + accm[a][0] * scm;
        float oy = accp[a][1] * scp + accm[a][1] * scm;
        float oz = accp[a][2] * scp + accm[a][2] * scm;
        float ow = accp[a][3] * scp + accm[a][3] * scm;

        __nv_bfloat16 h0 = __float2bfloat16(ox);
        __nv_bfloat16 h1 = __float2bfloat16(oy);
        __nv_bfloat16 h2 = __float2bfloat16(oz);
        __nv_bfloat16 h3 = __float2bfloat16(ow);
        __nv_bfloat16 l0b = __float2bfloat16(ox - __bfloat162float(h0));
        __nv_bfloat16 l1b = __float2bfloat16(oy - __bfloat162float(h1));
        __nv_bfloat16 l2b = __float2bfloat16(oz - __bfloat162float(h2));
        __nv_bfloat16 l3b = __float2bfloat16(ow - __bfloat162float(h3));

        size_t m = (size_t)(b * LL + l0 + tok);
        int col = h * 64 + j * 4;
        __nv_bfloat162* ph = (__nv_bfloat162*)(g_apack + m * 2048 + col);
        ph[0] = __halves2bfloat162(h0, h1);
        ph[1] = __halves2bfloat162(h2, h3);
        __nv_bfloat162* pl = (__nv_bfloat162*)(g_apack + m * 2048 + 1024 + col);
        pl[0] = __halves2bfloat162(l0b, l1b);
        pl[1] = __halves2bfloat162(l2b, l3b);
    }
}

// ===========================================================================
// Launch
// ===========================================================================
extern "C" void kernel_launch(void* const* d_in, const int* in_sizes, int n_in,
                              void* d_out, int out_size)
{
    (void)in_sizes; (void)n_in; (void)out_size;
    const float* q    = (const float*)d_in[0];
    const float* v    = (const float*)d_in[1];
    const float* k    = (const float*)d_in[2];
    const float* mask = (const float*)d_in[3];
    const float* Wq   = (const float*)d_in[4];
    const float* bq   = (const float*)d_in[5];
    const float* Wk   = (const float*)d_in[6];
    const float* bk   = (const float*)d_in[7];
    const float* Wv   = (const float*)d_in[8];
    const float* bv   = (const float*)d_in[9];
    const float* Wo   = (const float*)d_in[10];
    const float* bo   = (const float*)d_in[11];
    float* out = (float*)d_out;

    float *p_qp, *p_kp, *p_vp;
    __nv_bfloat16 *p_apack, *p_wpack;
    cudaGetSymbolAddress((void**)&p_qp, g_qp);
    cudaGetSymbolAddress((void**)&p_kp, g_kp);
    cudaGetSymbolAddress((void**)&p_vp, g_vp);
    cudaGetSymbolAddress((void**)&p_apack, g_apack);
    cudaGetSymbolAddress((void**)&p_wpack, g_wpack);

    static bool attr_set = false;
    if (!attr_set) {
        cudaFuncSetAttribute(gemm_hmma, cudaFuncAttributeMaxDynamicSharedMemorySize, GEMM_SMEM);
        attr_set = true;
    }

    dim3 ggrid(DD / GBN, MTOT / GBM);  // (8, 128)

    // Q projection
    pack_hilo<<<MTOT, 256>>>(q, p_apack);
    pack_hilo<<<1024, 256>>>(Wq, p_wpack);
    gemm_hmma<<<ggrid, 256, GEMM_SMEM>>>(p_apack, p_wpack, bq, p_qp);
    // K projection
    pack_hilo<<<MTOT, 256>>>(k, p_apack);
    pack_hilo<<<1024, 256>>>(Wk, p_wpack);
    gemm_hmma<<<ggrid, 256, GEMM_SMEM>>>(p_apack, p_wpack, bk, p_kp);
    // V projection
    pack_hilo<<<MTOT, 256>>>(v, p_apack);
    pack_hilo<<<1024, 256>>>(Wv, p_wpack);
    gemm_hmma<<<ggrid, 256, GEMM_SMEM>>>(p_apack, p_wpack, bv, p_vp);

    // sigmoid + (K: /L2) + L2 normalize, in place
    qk_epilogue<<<dim3((BB * LL * HH) / 8, 2), 256>>>();

    // kv matrices (deterministic partial + reduce)
    kv_partial<<<dim3(BB * HH, NCHUNK), 256>>>(mask);
    kv_reduce<<<(BB * HH * 2 * DH * DH) / 256, 256>>>();

    // heads = l2norm(Q@kv+) + l2norm(Q@kv-), packed bf16 hi/lo into g_apack
    qkv_apply<<<dim3(BB * HH, LL / 64), 256>>>();

    // Output projection
    pack_hilo<<<1024, 256>>>(Wo, p_wpack);
    gemm_hmma<<<ggrid, 256, GEMM_SMEM>>>(p_apack, p_wpack, bo, out);
}

// round 16
// speedup vs baseline: 1.0152x; 1.0000x over previous
#include <cuda_runtime.h>
#include <cuda_bf16.h>
#include <stdint.h>
#include <math.h>

// Problem constants (fixed shapes)
#define BB 4
#define LL 4096
#define DD 1024
#define HH 16
#define DH 64
#define NCHUNK 8
#define CHUNKL (LL / NCHUNK)   // 512
#define MTOT (BB * LL)         // 16384

// ===========================================================================
// Scratch (static __device__ arrays; no allocation anywhere)
// ===========================================================================
__device__ __align__(16) float g_qp[(size_t)BB * LL * DD];
__device__ __align__(16) float g_kp[(size_t)BB * LL * DD];
__device__ __align__(16) float g_vp[(size_t)BB * LL * DD];
__device__ __align__(16) float g_kvpart[(size_t)NCHUNK * BB * HH * 2 * DH * DH];
__device__ __align__(16) float g_kv[(size_t)BB * HH * 2 * DH * DH];
// bf16 hi/lo packed operands: row-major, row stride 2048 (cols 0..1023 = hi, 1024..2047 = lo)
__device__ __align__(16) __nv_bfloat16 g_apack[(size_t)MTOT * 2048];
__device__ __align__(16) __nv_bfloat16 g_wpack[(size_t)1024 * 2048];

// ===========================================================================
// pack_hilo: fp32 (rows x 1024) -> bf16 (rows x 2048) [hi | lo]
// ===========================================================================
__global__ void pack_hilo(const float* __restrict__ src, __nv_bfloat16* __restrict__ dst)
{
    size_t idx = (size_t)blockIdx.x * 256 + threadIdx.x;   // group-of-4 index
    size_t row = idx >> 8;
    int c4 = (int)(idx & 255) << 2;
    float4 x = *(const float4*)(src + row * 1024 + c4);
    __nv_bfloat16 h0 = __float2bfloat16(x.x);
    __nv_bfloat16 h1 = __float2bfloat16(x.y);
    __nv_bfloat16 h2 = __float2bfloat16(x.z);
    __nv_bfloat16 h3 = __float2bfloat16(x.w);
    __nv_bfloat16 l0 = __float2bfloat16(x.x - __bfloat162float(h0));
    __nv_bfloat16 l1 = __float2bfloat16(x.y - __bfloat162float(h1));
    __nv_bfloat16 l2 = __float2bfloat16(x.z - __bfloat162float(h2));
    __nv_bfloat16 l3 = __float2bfloat16(x.w - __bfloat162float(h3));
    __nv_bfloat162* ph = (__nv_bfloat162*)(dst + row * 2048 + c4);
    ph[0] = __halves2bfloat162(h0, h1);
    ph[1] = __halves2bfloat162(h2, h3);
    __nv_bfloat162* pl = (__nv_bfloat162*)(dst + row * 2048 + 1024 + c4);
    pl[0] = __halves2bfloat162(l0, l1);
    pl[1] = __halves2bfloat162(l2, l3);
}

// ===========================================================================
// HMMA (mma.sync) bf16-split GEMM: C[m,n] = sum_k A[m,k]*W[n,k] + bias[n]
// A, W packed hi/lo bf16 (row stride 2048). Virtual K' = 3072:
//   region 0: Ahi*Whi, region 1: Ahi*Wlo, region 2: Alo*Whi
// CTA tile 128x128, 8 warps (warp tile m32 x n64), K-chunk 64 bf16,
// cp.async double-buffered smem, ldmatrix operand loads, XOR-128B swizzle.
// ===========================================================================
#define GBM 128
#define GBN 128
#define GSTAGE 32768                       // A 16KB + B 16KB per stage
#define GEMM_SMEM (2 * GSTAGE + 1024)
#define NVCHUNK 48                         // 3 regions x 16 chunks of 64

__device__ __forceinline__ uint32_t smem_u32(const void* p) {
    uint32_t a;
    asm("{ .reg .u64 t; cvta.to.shared.u64 t, %1; cvt.u32.u64 %0, t; }" : "=r"(a) : "l"(p));
    return a;
}

__global__ __launch_bounds__(256)
void gemm_hmma(const __nv_bfloat16* __restrict__ A, const __nv_bfloat16* __restrict__ W,
               const float* __restrict__ bias, float* __restrict__ C)
{
    extern __shared__ char dyn_smem[];
    // 1024-align the stage base (swizzle consistency + clean banking)
    const uint32_t dyn_base = smem_u32(dyn_smem);
    const uint32_t sbase = (dyn_base + 1023) & ~1023u;
    char* sb = dyn_smem + (sbase - dyn_base);

    const int tid = threadIdx.x;
    const int wid = tid >> 5, lane = tid & 31;
    const int wm = wid & 3, wn = wid >> 2;         // warp origin (wm*32, wn*64)
    const int bm = blockIdx.y * GBM;
    const int bn = blockIdx.x * GBN;

    float acc[2][8][4];
    #pragma unroll
    for (int mi = 0; mi < 2; mi++)
        #pragma unroll
        for (int t = 0; t < 8; t++)
            #pragma unroll
            for (int r = 0; r < 4; r++) acc[mi][t][r] = 0.0f;

    // ---- async chunk loader: 128x64 bf16 A tile + 128x64 bf16 B tile ----
    auto load_chunk = [&](int c, int s) {
        const int r = c >> 4, kc = c & 15;
        const int acol = (r == 2 ? 1024 : 0) + kc * 64;   // Alo only in region 2
        const int wcol = (r == 1 ? 1024 : 0) + kc * 64;   // Wlo only in region 1
        const uint32_t abase = sbase + (uint32_t)s * GSTAGE;
        const uint32_t bbase = abase + 16384;
        #pragma unroll
        for (int i = 0; i < 4; ++i) {
            int idx = tid + i * 256;
            int row = idx >> 3, seg = idx & 7;
            uint32_t off = (uint32_t)(row * 128 + seg * 16);
            off ^= (off >> 3) & 0x70;
            const void* gp = A + (size_t)(bm + row) * 2048 + acol + seg * 8;
            asm volatile("cp.async.cg.shared.global [%0], [%1], 16;"
                         :: "r"(abase + off), "l"(gp) : "memory");
        }
        #pragma unroll
        for (int i = 0; i < 4; ++i) {
            int idx = tid + i * 256;
            int row = idx >> 3, seg = idx & 7;
            uint32_t off = (uint32_t)(row * 128 + seg * 16);
            off ^= (off >> 3) & 0x70;
            const void* gp = W + (size_t)(bn + row) * 2048 + wcol + seg * 8;
            asm volatile("cp.async.cg.shared.global [%0], [%1], 16;"
                         :: "r"(bbase + off), "l"(gp) : "memory");
        }
        asm volatile("cp.async.commit_group;" ::: "memory");
    };

    load_chunk(0, 0);

    for (int c = 0; c < NVCHUNK; ++c) {
        asm volatile("cp.async.wait_group 0;" ::: "memory");
        __syncthreads();
        if (c + 1 < NVCHUNK) load_chunk(c + 1, (c + 1) & 1);

        const uint32_t sA = sbase + (uint32_t)(c & 1) * GSTAGE;
        const uint32_t sB = sA + 16384;

        #pragma unroll
        for (int ks = 0; ks < 4; ++ks) {
            const int cb = ks * 32;   // byte offset of this k16 within the 128B row

            uint32_t a[2][4];
            #pragma unroll
            for (int mi = 0; mi < 2; ++mi) {
                int row = wm * 32 + mi * 16 + (lane & 15);
                uint32_t off = (uint32_t)(row * 128 + cb + ((lane >> 4) << 4));
                off ^= (off >> 3) & 0x70;
                asm volatile("ldmatrix.sync.aligned.m8n8.x4.shared.b16 {%0,%1,%2,%3}, [%4];"
                             : "=r"(a[mi][0]), "=r"(a[mi][1]), "=r"(a[mi][2]), "=r"(a[mi][3])
                             : "r"(sA + off));
            }
            uint32_t b[4][4];
            #pragma unroll
            for (int g = 0; g < 4; ++g) {
                int nrow = wn * 64 + g * 16 + ((lane >> 3) & 1) * 8 + (lane & 7);
                uint32_t off = (uint32_t)(nrow * 128 + cb + ((lane >> 4) << 4));
                off ^= (off >> 3) & 0x70;
                asm volatile("ldmatrix.sync.aligned.m8n8.x4.shared.b16 {%0,%1,%2,%3}, [%4];"
                             : "=r"(b[g][0]), "=r"(b[g][1]), "=r"(b[g][2]), "=r"(b[g][3])
                             : "r"(sB + off));
            }
            #pragma unroll
            for (int mi = 0; mi < 2; ++mi)
                #pragma unroll
                for (int t = 0; t < 8; ++t) {
                    const int g = t >> 1, hi = t & 1;
                    asm volatile(
                        "mma.sync.aligned.m16n8k16.row.col.f32.bf16.bf16.f32 "
                        "{%0,%1,%2,%3}, {%4,%5,%6,%7}, {%8,%9}, {%0,%1,%2,%3};"
                        : "+f"(acc[mi][t][0]), "+f"(acc[mi][t][1]),
                          "+f"(acc[mi][t][2]), "+f"(acc[mi][t][3])
                        : "r"(a[mi][0]), "r"(a[mi][1]), "r"(a[mi][2]), "r"(a[mi][3]),
                          "r"(b[g][hi]), "r"(b[g][2 + hi]));
                }
        }
    }

    // ---- epilogue: add bias, store fp32 ----
    const int g4 = lane >> 2, t4 = lane & 3;
    #pragma unroll
    for (int mi = 0; mi < 2; ++mi) {
        const int r0 = bm + wm * 32 + mi * 16 + g4;
        #pragma unroll
        for (int t = 0; t < 8; ++t) {
            const int col = bn + wn * 64 + t * 8 + t4 * 2;
            float2 bv = *(const float2*)(bias + col);
            float2 v0, v1;
            v0.x = acc[mi][t][0] + bv.x; v0.y = acc[mi][t][1] + bv.y;
            v1.x = acc[mi][t][2] + bv.x; v1.y = acc[mi][t][3] + bv.y;
            *(float2*)(C + (size_t)r0 * DD + col) = v0;
            *(float2*)(C + (size_t)(r0 + 8) * DD + col) = v1;
        }
    }
}

// ===========================================================================
// Q/K epilogue (in place): sigmoid, (K: /L2), L2-normalize each 64-elem head
// ===========================================================================
__global__ void qk_epilogue()
{
    const int warp = threadIdx.x >> 5;
    const int lane = threadIdx.x & 31;
    const size_t g = (size_t)blockIdx.x * 8 + warp;
    float* p = blockIdx.y ? g_kp : g_qp;
    const float pre = blockIdx.y ? (1.0f / (float)LL) : 1.0f;

    const size_t base = g * 64;
    float x0 = p[base + lane];
    float x1 = p[base + lane + 32];
    float s0 = pre / (1.0f + expf(-x0));
    float s1 = pre / (1.0f + expf(-x1));
    float ss = s0 * s0 + s1 * s1;
    #pragma unroll
    for (int off = 16; off > 0; off >>= 1)
        ss += __shfl_xor_sync(0xffffffffu, ss, off);
    float sc = 1.0f / fmaxf(sqrtf(ss), 1e-12f);
    p[base + lane]      = s0 * sc;
    p[base + lane + 32] = s1 * sc;
}

// ===========================================================================
// kv partial sums (deterministic), then reduce
// ===========================================================================
__global__ __launch_bounds__(256, 4)
void kv_partial(const float* __restrict__ mask)
{
    const int bh = blockIdx.x;
    const int chunk = blockIdx.y;
    const int b = bh >> 4, h = bh & 15;

    __shared__ float sK[8][64];
    __shared__ float sV[8][64];

    const int t = threadIdx.x;
    const int i = t >> 4, j = t & 15;
    const int l0base = chunk * CHUNKL;

    float accp[4][4], accm[4][4];
    #pragma unroll
    for (int a = 0; a < 4; a++)
        #pragma unroll
        for (int c = 0; c < 4; c++) { accp[a][c] = 0.0f; accm[a][c] = 0.0f; }

    for (int l0 = 0; l0 < CHUNKL; l0 += 8) {
        __syncthreads();
        if (t < 128) {
            int lrow = t >> 4, c4 = (t & 15) << 2;
            int l = l0base + l0 + lrow;
            float4 k4 = *(const float4*)(g_kp + ((size_t)(b * LL + l)) * DD + h * 64 + c4);
            *(float4*)&sK[lrow][c4] = k4;
        } else {
            int tt = t - 128;
            int lrow = tt >> 4, c4 = (tt & 15) << 2;
            int l = l0base + l0 + lrow;
            float m = mask[b * LL + l];
            float4 v4 = *(const float4*)(g_vp + ((size_t)(b * LL + l)) * DD + h * 64 + c4);
            v4.x *= m; v4.y *= m; v4.z *= m; v4.w *= m;
            *(float4*)&sV[lrow][c4] = v4;
        }
        __syncthreads();
        #pragma unroll
        for (int ll = 0; ll < 8; ll++) {
            float4 k4 = *(const float4*)&sK[ll][i * 4];
            float4 v4 = *(const float4*)&sV[ll][j * 4];
            float kk[4] = {k4.x, k4.y, k4.z, k4.w};
            float vv[4] = {v4.x, v4.y, v4.z, v4.w};
            float vps[4], vms[4];
            #pragma unroll
            for (int c = 0; c < 4; c++) {
                vps[c] = fmaxf(vv[c], 0.0f);
                vms[c] = vv[c] - vps[c];
            }
            #pragma unroll
            for (int a = 0; a < 4; a++)
                #pragma unroll
                for (int c = 0; c < 4; c++) {
                    accp[a][c] = fmaf(kk[a], vps[c], accp[a][c]);
                    accm[a][c] = fmaf(kk[a], vms[c], accm[a][c]);
                }
        }
    }

    const size_t base = ((size_t)(chunk * 64 + bh)) * 2 * (DH * DH);
    #pragma unroll
    for (int a = 0; a < 4; a++) {
        int d = i * 4 + a;
        float4 p4 = make_float4(accp[a][0], accp[a][1], accp[a][2], accp[a][3]);
        float4 m4 = make_float4(accm[a][0], accm[a][1], accm[a][2], accm[a][3]);
        *(float4*)(g_kvpart + base + d * 64 + j * 4) = p4;
        *(float4*)(g_kvpart + base + DH * DH + d * 64 + j * 4) = m4;
    }
}

__global__ void kv_reduce()
{
    const size_t stride = (size_t)BB * HH * 2 * DH * DH;
    size_t idx = (size_t)blockIdx.x * 256 + threadIdx.x;
    float s = 0.0f;
    #pragma unroll
    for (int ch = 0; ch < NCHUNK; ch++)
        s += g_kvpart[(size_t)ch * stride + idx];
    g_kv[idx] = s;
}

// ===========================================================================
// Apply: heads = l2norm(Q@kv+) + l2norm(Q@kv-); output packed bf16 hi/lo
// straight into g_apack (for the Wo GEMM).
// ===========================================================================
__global__ __launch_bounds__(256)
void qkv_apply()
{
    const int bh = blockIdx.x;
    const int tile = blockIdx.y;
    const int b = bh >> 4, h = bh & 15;

    __shared__ float Qs[64][64];
    __shared__ float kvp[64][64];
    __shared__ float kvm[64][64];

    const int t = threadIdx.x;
    const size_t kvbase = (size_t)bh * 2 * (DH * DH);

    #pragma unroll
    for (int r = 0; r < 4; r++) {
        int idx = r * 256 + t;
        ((float4*)kvp)[idx] = ((const float4*)(g_kv + kvbase))[idx];
        ((float4*)kvm)[idx] = ((const float4*)(g_kv + kvbase + DH * DH))[idx];
    }
    const int l0 = tile * 64;
    #pragma unroll
    for (int r = 0; r < 4; r++) {
        int tok = r * 16 + (t >> 4);
        int d4 = (t & 15) << 2;
        float4 q4 = *(const float4*)(g_qp + ((size_t)(b * LL + l0 + tok)) * DD + h * 64 + d4);
        Qs[d4 + 0][tok] = q4.x; Qs[d4 + 1][tok] = q4.y;
        Qs[d4 + 2][tok] = q4.z; Qs[d4 + 3][tok] = q4.w;
    }
    __syncthreads();

    const int i = t >> 4, j = t & 15;
    float accp[4][4], accm[4][4];
    #pragma unroll
    for (int a = 0; a < 4; a++)
        #pragma unroll
        for (int c = 0; c < 4; c++) { accp[a][c] = 0.0f; accm[a][c] = 0.0f; }

    #pragma unroll 8
    for (int d = 0; d < 64; d++) {
        float4 q4 = *(const float4*)&Qs[d][i * 4];
        float4 p4 = *(const float4*)&kvp[d][j * 4];
        float4 m4 = *(const float4*)&kvm[d][j * 4];
        float qq[4] = {q4.x, q4.y, q4.z, q4.w};
        float pp[4] = {p4.x, p4.y, p4.z, p4.w};
        float mm[4] = {m4.x, m4.y, m4.z, m4.w};
        #pragma unroll
        for (int a = 0; a < 4; a++)
            #pragma unroll
            for (int c = 0; c < 4; c++) {
                accp[a][c] = fmaf(qq[a], pp[c], accp[a][c]);
                accm[a][c] = fmaf(qq[a], mm[c], accm[a][c]);
            }
    }

    #pragma unroll
    for (int a = 0; a < 4; a++) {
        float sp = accp[a][0] * accp[a][0] + accp[a][1] * accp[a][1]
                 + accp[a][2] * accp[a][2] + accp[a][3] * accp[a][3];
        float sm = accm[a][0] * accm[a][0] + accm[a][1] * accm[a][1]
                 + accm[a][2] * accm[a][2] + accm[a][3] * accm[a][3];
        #pragma unroll
        for (int off = 8; off > 0; off >>= 1) {
            sp += __shfl_xor_sync(0xffffffffu, sp, off, 16);
            sm += __shfl_xor_sync(0xffffffffu, sm, off, 16);
        }
        float scp = 1.0f / fmaxf(sqrtf(sp), 1e-12f);
        float scm = 1.0f / fmaxf(sqrtf(sm), 1e-12f);
        int tok = i * 4 + a;
        float ox = accp[a][0] * scp + accm[a][0] * scm;
        float oy = accp[a][1] * scp + accm[a][1] * scm;
        float oz = accp[a][2] * scp + accm[a][2] * scm;
        float ow = accp[a][3] * scp + accm[a][3] * scm;

        __nv_bfloat16 h0 = __float2bfloat16(ox);
        __nv_bfloat16 h1 = __float2bfloat16(oy);
        __nv_bfloat16 h2 = __float2bfloat16(oz);
        __nv_bfloat16 h3 = __float2bfloat16(ow);
        __nv_bfloat16 l0b = __float2bfloat16(ox - __bfloat162float(h0));
        __nv_bfloat16 l1b = __float2bfloat16(oy - __bfloat162float(h1));
        __nv_bfloat16 l2b = __float2bfloat16(oz - __bfloat162float(h2));
        __nv_bfloat16 l3b = __float2bfloat16(ow - __bfloat162float(h3));

        size_t m = (size_t)(b * LL + l0 + tok);
        int col = h * 64 + j * 4;
        __nv_bfloat162* ph = (__nv_bfloat162*)(g_apack + m * 2048 + col);
        ph[0] = __halves2bfloat162(h0, h1);
        ph[1] = __halves2bfloat162(h2, h3);
        __nv_bfloat162* pl = (__nv_bfloat162*)(g_apack + m * 2048 + 1024 + col);
        pl[0] = __halves2bfloat162(l0b, l1b);
        pl[1] = __halves2bfloat162(l2b, l3b);
    }
}

// ===========================================================================
// Launch
// ===========================================================================
extern "C" void kernel_launch(void* const* d_in, const int* in_sizes, int n_in,
                              void* d_out, int out_size)
{
    (void)in_sizes; (void)n_in; (void)out_size;
    const float* q    = (const float*)d_in[0];
    const float* v    = (const float*)d_in[1];
    const float* k    = (const float*)d_in[2];
    const float* mask = (const float*)d_in[3];
    const float* Wq   = (const float*)d_in[4];
    const float* bq   = (const float*)d_in[5];
    const float* Wk   = (const float*)d_in[6];
    const float* bk   = (const float*)d_in[7];
    const float* Wv   = (const float*)d_in[8];
    const float* bv   = (const float*)d_in[9];
    const float* Wo   = (const float*)d_in[10];
    const float* bo   = (const float*)d_in[11];
    float* out = (float*)d_out;

    float *p_qp, *p_kp, *p_vp;
    __nv_bfloat16 *p_apack, *p_wpack;
    cudaGetSymbolAddress((void**)&p_qp, g_qp);
    cudaGetSymbolAddress((void**)&p_kp, g_kp);
    cudaGetSymbolAddress((void**)&p_vp, g_vp);
    cudaGetSymbolAddress((void**)&p_apack, g_apack);
    cudaGetSymbolAddress((void**)&p_wpack, g_wpack);

    static bool attr_set = false;
    if (!attr_set) {
        cudaFuncSetAttribute(gemm_hmma, cudaFuncAttributeMaxDynamicSharedMemorySize, GEMM_SMEM);
        attr_set = true;
    }

    dim3 ggrid(DD / GBN, MTOT / GBM);  // (8, 128)

    // Q projection
    pack_hilo<<<MTOT, 256>>>(q, p_apack);
    pack_hilo<<<1024, 256>>>(Wq, p_wpack);
    gemm_hmma<<<ggrid, 256, GEMM_SMEM>>>(p_apack, p_wpack, bq, p_qp);
    // K projection
    pack_hilo<<<MTOT, 256>>>(k, p_apack);
    pack_hilo<<<1024, 256>>>(Wk, p_wpack);
    gemm_hmma<<<ggrid, 256, GEMM_SMEM>>>(p_apack, p_wpack, bk, p_kp);
    // V projection
    pack_hilo<<<MTOT, 256>>>(v, p_apack);
    pack_hilo<<<1024, 256>>>(Wv, p_wpack);
    gemm_hmma<<<ggrid, 256, GEMM_SMEM>>>(p_apack, p_wpack, bv, p_vp);

    // sigmoid + (K: /L2) + L2 normalize, in place
    qk_epilogue<<<dim3((BB * LL * HH) / 8, 2), 256>>>();

    // kv matrices (deterministic partial + reduce)
    kv_partial<<<dim3(BB * HH, NCHUNK), 256>>>(mask);
    kv_reduce<<<(BB * HH * 2 * DH * DH) / 256, 256>>>();

    // heads = l2norm(Q@kv+) + l2norm(Q@kv-), packed bf16 hi/lo into g_apack
    qkv_apply<<<dim3(BB * HH, LL / 64), 256>>>();

    // Output projection
    pack_hilo<<<1024, 256>>>(Wo, p_wpack);
    gemm_hmma<<<ggrid, 256, GEMM_SMEM>>>(p_apack, p_wpack, bo, out);
}

// round 17
// speedup vs baseline: 1.0173x; 1.0021x over previous
#include <cuda_runtime.h>
#include <cuda_bf16.h>
#include <stdint.h>
#include <math.h>

// Problem constants (fixed shapes)
#define BB 4
#define LL 4096
#define DD 1024
#define HH 16
#define DH 64
#define NCHUNK 8
#define CHUNKL (LL / NCHUNK)   // 512
#define MTOT (BB * LL)         // 16384

// ===========================================================================
// Scratch (static __device__ arrays; no allocation anywhere)
// ===========================================================================
__device__ __align__(16) float g_qp[(size_t)BB * LL * DD];
__device__ __align__(16) float g_kp[(size_t)BB * LL * DD];
__device__ __align__(16) float g_vp[(size_t)BB * LL * DD];
__device__ __align__(16) float g_kvpart[(size_t)NCHUNK * BB * HH * 2 * DH * DH];
__device__ __align__(16) float g_kv[(size_t)BB * HH * 2 * DH * DH];
// bf16 hi/lo packed operands: row-major, row stride 2048 (cols 0..1023 = hi, 1024..2047 = lo)
__device__ __align__(16) __nv_bfloat16 g_apack[(size_t)MTOT * 2048];
__device__ __align__(16) __nv_bfloat16 g_wpack[(size_t)1024 * 2048];

// ===========================================================================
// pack_hilo: fp32 (rows x 1024) -> bf16 (rows x 2048) [hi | lo]
// ===========================================================================
__global__ void pack_hilo(const float* __restrict__ src, __nv_bfloat16* __restrict__ dst)
{
    size_t idx = (size_t)blockIdx.x * 256 + threadIdx.x;   // group-of-4 index
    size_t row = idx >> 8;
    int c4 = (int)(idx & 255) << 2;
    float4 x = *(const float4*)(src + row * 1024 + c4);
    __nv_bfloat16 h0 = __float2bfloat16(x.x);
    __nv_bfloat16 h1 = __float2bfloat16(x.y);
    __nv_bfloat16 h2 = __float2bfloat16(x.z);
    __nv_bfloat16 h3 = __float2bfloat16(x.w);
    __nv_bfloat16 l0 = __float2bfloat16(x.x - __bfloat162float(h0));
    __nv_bfloat16 l1 = __float2bfloat16(x.y - __bfloat162float(h1));
    __nv_bfloat16 l2 = __float2bfloat16(x.z - __bfloat162float(h2));
    __nv_bfloat16 l3 = __float2bfloat16(x.w - __bfloat162float(h3));
    __nv_bfloat162* ph = (__nv_bfloat162*)(dst + row * 2048 + c4);
    ph[0] = __halves2bfloat162(h0, h1);
    ph[1] = __halves2bfloat162(h2, h3);
    __nv_bfloat162* pl = (__nv_bfloat162*)(dst + row * 2048 + 1024 + c4);
    pl[0] = __halves2bfloat162(l0, l1);
    pl[1] = __halves2bfloat162(l2, l3);
}

// ===========================================================================
// HMMA (mma.sync) bf16-split GEMM: C[m,n] = sum_k A[m,k]*W[n,k] + bias[n]
// A, W packed hi/lo bf16 (row stride 2048). Virtual K' = 3072:
//   region 0: Ahi*Whi, region 1: Ahi*Wlo, region 2: Alo*Whi
// CTA tile 128x128, 8 warps (warp tile m32 x n64), K-chunk 64 bf16,
// cp.async double-buffered smem, ldmatrix operand loads, XOR-128B swizzle.
// ===========================================================================
#define GBM 128
#define GBN 128
#define GSTAGE 32768                       // A 16KB + B 16KB per stage
#define GEMM_SMEM (2 * GSTAGE + 1024)
#define NVCHUNK 48                         // 3 regions x 16 chunks of 64

__device__ __forceinline__ uint32_t smem_u32(const void* p) {
    uint32_t a;
    asm("{ .reg .u64 t; cvta.to.shared.u64 t, %1; cvt.u32.u64 %0, t; }" : "=r"(a) : "l"(p));
    return a;
}

__global__ __launch_bounds__(256)
void gemm_hmma(const __nv_bfloat16* __restrict__ A, const __nv_bfloat16* __restrict__ W,
               const float* __restrict__ bias, float* __restrict__ C)
{
    extern __shared__ char dyn_smem[];
    // 1024-align the stage base (swizzle consistency + clean banking)
    const uint32_t dyn_base = smem_u32(dyn_smem);
    const uint32_t sbase = (dyn_base + 1023) & ~1023u;
    char* sb = dyn_smem + (sbase - dyn_base);

    const int tid = threadIdx.x;
    const int wid = tid >> 5, lane = tid & 31;
    const int wm = wid & 3, wn = wid >> 2;         // warp origin (wm*32, wn*64)
    const int bm = blockIdx.y * GBM;
    const int bn = blockIdx.x * GBN;

    float acc[2][8][4];
    #pragma unroll
    for (int mi = 0; mi < 2; mi++)
        #pragma unroll
        for (int t = 0; t < 8; t++)
            #pragma unroll
            for (int r = 0; r < 4; r++) acc[mi][t][r] = 0.0f;

    // ---- async chunk loader: 128x64 bf16 A tile + 128x64 bf16 B tile ----
    auto load_chunk = [&](int c, int s) {
        const int r = c >> 4, kc = c & 15;
        const int acol = (r == 2 ? 1024 : 0) + kc * 64;   // Alo only in region 2
        const int wcol = (r == 1 ? 1024 : 0) + kc * 64;   // Wlo only in region 1
        const uint32_t abase = sbase + (uint32_t)s * GSTAGE;
        const uint32_t bbase = abase + 16384;
        #pragma unroll
        for (int i = 0; i < 4; ++i) {
            int idx = tid + i * 256;
            int row = idx >> 3, seg = idx & 7;
            uint32_t off = (uint32_t)(row * 128 + seg * 16);
            off ^= (off >> 3) & 0x70;
            const void* gp = A + (size_t)(bm + row) * 2048 + acol + seg * 8;
            asm volatile("cp.async.cg.shared.global [%0], [%1], 16;"
                         :: "r"(abase + off), "l"(gp) : "memory");
        }
        #pragma unroll
        for (int i = 0; i < 4; ++i) {
            int idx = tid + i * 256;
            int row = idx >> 3, seg = idx & 7;
            uint32_t off = (uint32_t)(row * 128 + seg * 16);
            off ^= (off >> 3) & 0x70;
            const void* gp = W + (size_t)(bn + row) * 2048 + wcol + seg * 8;
            asm volatile("cp.async.cg.shared.global [%0], [%1], 16;"
                         :: "r"(bbase + off), "l"(gp) : "memory");
        }
        asm volatile("cp.async.commit_group;" ::: "memory");
    };

    load_chunk(0, 0);

    for (int c = 0; c < NVCHUNK; ++c) {
        asm volatile("cp.async.wait_group 0;" ::: "memory");
        __syncthreads();
        if (c + 1 < NVCHUNK) load_chunk(c + 1, (c + 1) & 1);

        const uint32_t sA = sbase + (uint32_t)(c & 1) * GSTAGE;
        const uint32_t sB = sA + 16384;

        #pragma unroll
        for (int ks = 0; ks < 4; ++ks) {
            const int cb = ks * 32;   // byte offset of this k16 within the 128B row

            uint32_t a[2][4];
            #pragma unroll
            for (int mi = 0; mi < 2; ++mi) {
                int row = wm * 32 + mi * 16 + (lane & 15);
                uint32_t off = (uint32_t)(row * 128 + cb + ((lane >> 4) << 4));
                off ^= (off >> 3) & 0x70;
                asm volatile("ldmatrix.sync.aligned.m8n8.x4.shared.b16 {%0,%1,%2,%3}, [%4];"
                             : "=r"(a[mi][0]), "=r"(a[mi][1]), "=r"(a[mi][2]), "=r"(a[mi][3])
                             : "r"(sA + off));
            }
            uint32_t b[4][4];
            #pragma unroll
            for (int g = 0; g < 4; ++g) {
                int nrow = wn * 64 + g * 16 + ((lane >> 3) & 1) * 8 + (lane & 7);
                uint32_t off = (uint32_t)(nrow * 128 + cb + ((lane >> 4) << 4));
                off ^= (off >> 3) & 0x70;
                asm volatile("ldmatrix.sync.aligned.m8n8.x4.shared.b16 {%0,%1,%2,%3}, [%4];"
                             : "=r"(b[g][0]), "=r"(b[g][1]), "=r"(b[g][2]), "=r"(b[g][3])
                             : "r"(sB + off));
            }
            #pragma unroll
            for (int mi = 0; mi < 2; ++mi)
                #pragma unroll
                for (int t = 0; t < 8; ++t) {
                    const int g = t >> 1, hi = t & 1;
                    asm volatile(
                        "mma.sync.aligned.m16n8k16.row.col.f32.bf16.bf16.f32 "
                        "{%0,%1,%2,%3}, {%4,%5,%6,%7}, {%8,%9}, {%0,%1,%2,%3};"
                        : "+f"(acc[mi][t][0]), "+f"(acc[mi][t][1]),
                          "+f"(acc[mi][t][2]), "+f"(acc[mi][t][3])
                        : "r"(a[mi][0]), "r"(a[mi][1]), "r"(a[mi][2]), "r"(a[mi][3]),
                          "r"(b[g][hi]), "r"(b[g][2 + hi]));
                }
        }
    }

    // ---- epilogue: add bias, store fp32 ----
    const int g4 = lane >> 2, t4 = lane & 3;
    #pragma unroll
    for (int mi = 0; mi < 2; ++mi) {
        const int r0 = bm + wm * 32 + mi * 16 + g4;
        #pragma unroll
        for (int t = 0; t < 8; ++t) {
            const int col = bn + wn * 64 + t * 8 + t4 * 2;
            float2 bv = *(const float2*)(bias + col);
            float2 v0, v1;
            v0.x = acc[mi][t][0] + bv.x; v0.y = acc[mi][t][1] + bv.y;
            v1.x = acc[mi][t][2] + bv.x; v1.y = acc[mi][t][3] + bv.y;
            *(float2*)(C + (size_t)r0 * DD + col) = v0;
            *(float2*)(C + (size_t)(r0 + 8) * DD + col) = v1;
        }
    }
}

// ===========================================================================
// Q/K epilogue (in place): sigmoid, (K: /L2), L2-normalize each 64-elem head
// ===========================================================================
__global__ void qk_epilogue()
{
    const int warp = threadIdx.x >> 5;
    const int lane = threadIdx.x & 31;
    const size_t g = (size_t)blockIdx.x * 8 + warp;
    float* p = blockIdx.y ? g_kp : g_qp;
    const float pre = blockIdx.y ? (1.0f / (float)LL) : 1.0f;

    const size_t base = g * 64;
    float x0 = p[base + lane];
    float x1 = p[base + lane + 32];
    float s0 = pre / (1.0f + expf(-x0));
    float s1 = pre / (1.0f + expf(-x1));
    float ss = s0 * s0 + s1 * s1;
    #pragma unroll
    for (int off = 16; off > 0; off >>= 1)
        ss += __shfl_xor_sync(0xffffffffu, ss, off);
    float sc = 1.0f / fmaxf(sqrtf(ss), 1e-12f);
    p[base + lane]      = s0 * sc;
    p[base + lane + 32] = s1 * sc;
}

// ===========================================================================
// kv partial sums (deterministic), then reduce
// ===========================================================================
__global__ __launch_bounds__(256, 4)
void kv_partial(const float* __restrict__ mask)
{
    const int bh = blockIdx.x;
    const int chunk = blockIdx.y;
    const int b = bh >> 4, h = bh & 15;

    __shared__ float sK[8][64];
    __shared__ float sV[8][64];

    const int t = threadIdx.x;
    const int i = t >> 4, j = t & 15;
    const int l0base = chunk * CHUNKL;

    float accp[4][4], accm[4][4];
    #pragma unroll
    for (int a = 0; a < 4; a++)
        #pragma unroll
        for (int c = 0; c < 4; c++) { accp[a][c] = 0.0f; accm[a][c] = 0.0f; }

    for (int l0 = 0; l0 < CHUNKL; l0 += 8) {
        __syncthreads();
        if (t < 128) {
            int lrow = t >> 4, c4 = (t & 15) << 2;
            int l = l0base + l0 + lrow;
            float4 k4 = *(const float4*)(g_kp + ((size_t)(b * LL + l)) * DD + h * 64 + c4);
            *(float4*)&sK[lrow][c4] = k4;
        } else {
            int tt = t - 128;
            int lrow = tt >> 4, c4 = (tt & 15) << 2;
            int l = l0base + l0 + lrow;
            float m = mask[b * LL + l];
            float4 v4 = *(const float4*)(g_vp + ((size_t)(b * LL + l)) * DD + h * 64 + c4);
            v4.x *= m; v4.y *= m; v4.z *= m; v4.w *= m;
            *(float4*)&sV[lrow][c4] = v4;
        }
        __syncthreads();
        #pragma unroll
        for (int ll = 0; ll < 8; ll++) {
            float4 k4 = *(const float4*)&sK[ll][i * 4];
            float4 v4 = *(const float4*)&sV[ll][j * 4];
            float kk[4] = {k4.x, k4.y, k4.z, k4.w};
            float vv[4] = {v4.x, v4.y, v4.z, v4.w};
            float vps[4], vms[4];
            #pragma unroll
            for (int c = 0; c < 4; c++) {
                vps[c] = fmaxf(vv[c], 0.0f);
                vms[c] = vv[c] - vps[c];
            }
            #pragma unroll
            for (int a = 0; a < 4; a++)
                #pragma unroll
                for (int c = 0; c < 4; c++) {
                    accp[a][c] = fmaf(kk[a], vps[c], accp[a][c]);
                    accm[a][c] = fmaf(kk[a], vms[c], accm[a][c]);
                }
        }
    }

    const size_t base = ((size_t)(chunk * 64 + bh)) * 2 * (DH * DH);
    #pragma unroll
    for (int a = 0; a < 4; a++) {
        int d = i * 4 + a;
        float4 p4 = make_float4(accp[a][0], accp[a][1], accp[a][2], accp[a][3]);
        float4 m4 = make_float4(accm[a][0], accm[a][1], accm[a][2], accm[a][3]);
        *(float4*)(g_kvpart + base + d * 64 + j * 4) = p4;
        *(float4*)(g_kvpart + base + DH * DH + d * 64 + j * 4) = m4;
    }
}

__global__ void kv_reduce()
{
    const size_t stride = (size_t)BB * HH * 2 * DH * DH;
    size_t idx = (size_t)blockIdx.x * 256 + threadIdx.x;
    float s = 0.0f;
    #pragma unroll
    for (int ch = 0; ch < NCHUNK; ch++)
        s += g_kvpart[(size_t)ch * stride + idx];
    g_kv[idx] = s;
}

// ===========================================================================
// Apply: heads = l2norm(Q@kv+) + l2norm(Q@kv-); output packed bf16 hi/lo
// straight into g_apack (for the Wo GEMM).
// ===========================================================================
__global__ __launch_bounds__(256)
void qkv_apply()
{
    const int bh = blockIdx.x;
    const int tile = blockIdx.y;
    const int b = bh >> 4, h = bh & 15;

    __shared__ float Qs[64][64];
    __shared__ float kvp[64][64];
    __shared__ float kvm[64][64];

    const int t = threadIdx.x;
    const size_t kvbase = (size_t)bh * 2 * (DH * DH);

    #pragma unroll
    for (int r = 0; r < 4; r++) {
        int idx = r * 256 + t;
        ((float4*)kvp)[idx] = ((const float4*)(g_kv + kvbase))[idx];
        ((float4*)kvm)[idx] = ((const float4*)(g_kv + kvbase + DH * DH))[idx];
    }
    const int l0 = tile * 64;
    #pragma unroll
    for (int r = 0; r < 4; r++) {
        int tok = r * 16 + (t >> 4);
        int d4 = (t & 15) << 2;
        float4 q4 = *(const float4*)(g_qp + ((size_t)(b * LL + l0 + tok)) * DD + h * 64 + d4);
        Qs[d4 + 0][tok] = q4.x; Qs[d4 + 1][tok] = q4.y;
        Qs[d4 + 2][tok] = q4.z; Qs[d4 + 3][tok] = q4.w;
    }
    __syncthreads();

    const int i = t >> 4, j = t & 15;
    float accp[4][4], accm[4][4];
    #pragma unroll
    for (int a = 0; a < 4; a++)
        #pragma unroll
        for (int c = 0; c < 4; c++) { accp[a][c] = 0.0f; accm[a][c] = 0.0f; }

    #pragma unroll 8
    for (int d = 0; d < 64; d++) {
        float4 q4 = *(const float4*)&Qs[d][i * 4];
        float4 p4 = *(const float4*)&kvp[d][j * 4];
        float4 m4 = *(const float4*)&kvm[d][j * 4];
        float qq[4] = {q4.x, q4.y, q4.z, q4.w};
        float pp[4] = {p4.x, p4.y, p4.z, p4.w};
        float mm[4] = {m4.x, m4.y, m4.z, m4.w};
        #pragma unroll
        for (int a = 0; a < 4; a++)
            #pragma unroll
            for (int c = 0; c < 4; c++) {
                accp[a][c] = fmaf(qq[a], pp[c], accp[a][c]);
                accm[a][c] = fmaf(qq[a], mm[c], accm[a][c]);
            }
    }

    #pragma unroll
    for (int a = 0; a < 4; a++) {
        float sp = accp[a][0] * accp[a][0] + accp[a][1] * accp[a][1]
                 + accp[a][2] * accp[a][2] + accp[a][3] * accp[a][3];
        float sm = accm[a][0] * accm[a][0] + accm[a][1] * accm[a][1]
                 + accm[a][2] * accm[a][2] + accm[a][3] * accm[a][3];
        #pragma unroll
        for (int off = 8; off > 0; off >>= 1) {
            sp += __shfl_xor_sync(0xffffffffu, sp, off, 16);
            sm += __shfl_xor_sync(0xffffffffu, sm, off, 16);
        }
        float scp = 1.0f / fmaxf(sqrtf(sp), 1e-12f);
        float scm = 1.0f / fmaxf(sqrtf(sm), 1e-12f);
        int tok = i * 4 + a;
        float ox = accp[a][0] * scp + accm[a][0] * scm;
        float oy = accp[a][1] * scp + accm[a][1] * scm;
        float oz = accp[a][2] * scp + accm[a][2] * scm;
        float ow = accp[a][3] * scp + accm[a][3] * scm;

        __nv_bfloat16 h0 = __float2bfloat16(ox);
        __nv_bfloat16 h1 = __float2bfloat16(oy);
        __nv_bfloat16 h2 = __float2bfloat16(oz);
        __nv_bfloat16 h3 = __float2bfloat16(ow);
        __nv_bfloat16 l0b = __float2bfloat16(ox - __bfloat162float(h0));
        __nv_bfloat16 l1b = __float2bfloat16(oy - __bfloat162float(h1));
        __nv_bfloat16 l2b = __float2bfloat16(oz - __bfloat162float(h2));
        __nv_bfloat16 l3b = __float2bfloat16(ow - __bfloat162float(h3));

        size_t m = (size_t)(b * LL + l0 + tok);
        int col = h * 64 + j * 4;
        __nv_bfloat162* ph = (__nv_bfloat162*)(g_apack + m * 2048 + col);
        ph[0] = __halves2bfloat162(h0, h1);
        ph[1] = __halves2bfloat162(h2, h3);
        __nv_bfloat162* pl = (__nv_bfloat162*)(g_apack + m * 2048 + 1024 + col);
        pl[0] = __halves2bfloat162(l0b, l1b);
        pl[1] = __halves2bfloat162(l2b, l3b);
    }
}

// ===========================================================================
// Launch
// ===========================================================================
extern "C" void kernel_launch(void* const* d_in, const int* in_sizes, int n_in,
                              void* d_out, int out_size)
{
    (void)in_sizes; (void)n_in; (void)out_size;
    const float* q    = (const float*)d_in[0];
    const float* v    = (const float*)d_in[1];
    const float* k    = (const float*)d_in[2];
    const float* mask = (const float*)d_in[3];
    const float* Wq   = (const float*)d_in[4];
    const float* bq   = (const float*)d_in[5];
    const float* Wk   = (const float*)d_in[6];
    const float* bk   = (const float*)d_in[7];
    const float* Wv   = (const float*)d_in[8];
    const float* bv   = (const float*)d_in[9];
    const float* Wo   = (const float*)d_in[10];
    const float* bo   = (const float*)d_in[11];
    float* out = (float*)d_out;

    float *p_qp, *p_kp, *p_vp;
    __nv_bfloat16 *p_apack, *p_wpack;
    cudaGetSymbolAddress((void**)&p_qp, g_qp);
    cudaGetSymbolAddress((void**)&p_kp, g_kp);
    cudaGetSymbolAddress((void**)&p_vp, g_vp);
    cudaGetSymbolAddress((void**)&p_apack, g_apack);
    cudaGetSymbolAddress((void**)&p_wpack, g_wpack);

    static bool attr_set = false;
    if (!attr_set) {
        cudaFuncSetAttribute(gemm_hmma, cudaFuncAttributeMaxDynamicSharedMemorySize, GEMM_SMEM);
        attr_set = true;
    }

    dim3 ggrid(DD / GBN, MTOT / GBM);  // (8, 128)

    // Q projection
    pack_hilo<<<MTOT, 256>>>(q, p_apack);
    pack_hilo<<<1024, 256>>>(Wq, p_wpack);
    gemm_hmma<<<ggrid, 256, GEMM_SMEM>>>(p_apack, p_wpack, bq, p_qp);
    // K projection
    pack_hilo<<<MTOT, 256>>>(k, p_apack);
    pack_hilo<<<1024, 256>>>(Wk, p_wpack);
    gemm_hmma<<<ggrid, 256, GEMM_SMEM>>>(p_apack, p_wpack, bk, p_kp);
    // V projection
    pack_hilo<<<MTOT, 256>>>(v, p_apack);
    pack_hilo<<<1024, 256>>>(Wv, p_wpack);
    gemm_hmma<<<ggrid, 256, GEMM_SMEM>>>(p_apack, p_wpack, bv, p_vp);

    // sigmoid + (K: /L2) + L2 normalize, in place
    qk_epilogue<<<dim3((BB * LL * HH) / 8, 2), 256>>>();

    // kv matrices (deterministic partial + reduce)
    kv_partial<<<dim3(BB * HH, NCHUNK), 256>>>(mask);
    kv_reduce<<<(BB * HH * 2 * DH * DH) / 256, 256>>>();

    // heads = l2norm(Q@kv+) + l2norm(Q@kv-), packed bf16 hi/lo into g_apack
    qkv_apply<<<dim3(BB * HH, LL / 64), 256>>>();

    // Output projection
    pack_hilo<<<1024, 256>>>(Wo, p_wpack);
    gemm_hmma<<<ggrid, 256, GEMM_SMEM>>>(p_apack, p_wpack, bo, out);
}